// round 17
// baseline (speedup 1.0000x reference)
#include <cuda_runtime.h>

// Round 17 (= R16 retried; previous round was an infra failure, kernel never ran).
// R9 engine + split production:
//   Producer warps 0-3: build rows 0..23 of tile t+GRID (3 item-pairs/thread).
//   Consumer warps 4-7: GEMM tile t, store, THEN build rows 24..31 of tile
//     t+GRID (1 item-pair/thread) in their slack window.
// All 16 warps/SM now issue DRAM loads -> higher aggregate MLP.

#define N_NODES 50000
#define S_NEIGH 25
#define DIM     128
#define OUTD    128
#define KDIM    256
#define TM      32
#define THREADS 256
#define A_STRIDE 260            // floats per tile row (pad, 16B-aligned)
#define NT      3125            // 2*N_NODES / TM
#define GRID    296             // 2 persistent blocks per SM

typedef unsigned long long u64;

// ---- packed f32x2 helpers ----
__device__ __forceinline__ u64 fadd2(u64 a, u64 b) {
    u64 d; asm("add.rn.f32x2 %0, %1, %2;" : "=l"(d) : "l"(a), "l"(b)); return d;
}
__device__ __forceinline__ u64 fmul2(u64 a, u64 b) {
    u64 d; asm("mul.rn.f32x2 %0, %1, %2;" : "=l"(d) : "l"(a), "l"(b)); return d;
}
__device__ __forceinline__ u64 ffma2(u64 a, u64 b, u64 c) {
    u64 d; asm("fma.rn.f32x2 %0, %1, %2, %3;" : "=l"(d) : "l"(a), "l"(b), "l"(c)); return d;
}
__device__ __forceinline__ u64 bcast2(float x) {          // {x, x}
    u64 d; asm("mov.b64 %0, {%1, %1};" : "=l"(d) : "f"(x)); return d;
}
// 16B streaming load, evict-first, NON-volatile so ptxas can batch for MLP.
__device__ __forceinline__ ulonglong2 ldcs16(const float* p) {
    ulonglong2 v;
    asm("ld.global.cs.v2.u64 {%0, %1}, [%2];" : "=l"(v.x), "=l"(v.y) : "l"(p));
    return v;
}
__device__ __forceinline__ float4 ld4(const float* p) {
    return *reinterpret_cast<const float4*>(p);
}

// ---- one interleaved item-pair {ia, ib} of the cat tile ----
__device__ __forceinline__ void produce_pair(
    float* __restrict__ Adst, long t0, int ia, int ib,
    const float* __restrict__ src, const float* __restrict__ src_neg,
    const float* __restrict__ dst, const float* __restrict__ dst_neg,
    u64 inv2)
{
    const int ra = ia >> 5, d4a = (ia & 31) << 2;
    const int rb = ib >> 5, d4b = (ib & 31) << 2;

    const float *xpa, *npa, *xpb, *npb;
    {
        const long task = t0 + ra;
        if (task < N_NODES) { xpa = src + task * DIM; npa = src_neg + task * (long)(S_NEIGH * DIM); }
        else { const long rr = task - N_NODES; xpa = dst + rr * DIM; npa = dst_neg + rr * (long)(S_NEIGH * DIM); }
    }
    {
        const long task = t0 + rb;
        if (task < N_NODES) { xpb = src + task * DIM; npb = src_neg + task * (long)(S_NEIGH * DIM); }
        else { const long rr = task - N_NODES; xpb = dst + rr * DIM; npb = dst_neg + rr * (long)(S_NEIGH * DIM); }
    }

    const float* pa = npa + d4a;
    const float* pb = npb + d4b;

    u64 sa0 = 0ull, sa1 = 0ull, sb0 = 0ull, sb1 = 0ull;
    #pragma unroll
    for (int j = 0; j < S_NEIGH; j++) {
        const ulonglong2 va = ldcs16(pa + j * DIM);
        const ulonglong2 vb = ldcs16(pb + j * DIM);
        sa0 = fadd2(sa0, va.x); sa1 = fadd2(sa1, va.y);
        sb0 = fadd2(sb0, vb.x); sb1 = fadd2(sb1, vb.y);
    }

    const ulonglong2 xva = *reinterpret_cast<const ulonglong2*>(xpa + d4a);
    const ulonglong2 xvb = *reinterpret_cast<const ulonglong2*>(xpb + d4b);

    ulonglong2 ma, mb;
    ma.x = fmul2(sa0, inv2); ma.y = fmul2(sa1, inv2);
    mb.x = fmul2(sb0, inv2); mb.y = fmul2(sb1, inv2);

    *reinterpret_cast<ulonglong2*>(Adst + ra * A_STRIDE + d4a)       = xva;
    *reinterpret_cast<ulonglong2*>(Adst + ra * A_STRIDE + DIM + d4a) = ma;
    *reinterpret_cast<ulonglong2*>(Adst + rb * A_STRIDE + d4b)       = xvb;
    *reinterpret_cast<ulonglong2*>(Adst + rb * A_STRIDE + DIM + d4b) = mb;
}

__global__ __launch_bounds__(THREADS, 2)
void magg_kernel(const float* __restrict__ src,
                 const float* __restrict__ src_neg,
                 const float* __restrict__ dst,
                 const float* __restrict__ dst_neg,
                 const float* __restrict__ w,
                 float* __restrict__ out)
{
    __shared__ float A[2][TM][A_STRIDE];   // 66.6 KB double buffer

    const int tid  = threadIdx.x;
    const int wid  = tid >> 5;
    const int lane = tid & 31;

    u64 inv2; asm("mov.b64 %0, {%1, %1};" : "=l"(inv2) : "f"(1.0f / (float)S_NEIGH));

    // ---- prologue: all 256 threads build tile 0 ----
    {
        const long t0 = (long)blockIdx.x * TM;
        for (int i = tid; i < TM * (DIM / 4); i += 2 * THREADS)
            produce_pair(&A[0][0][0], t0, i, i + THREADS,
                         src, src_neg, dst, dst_neg, inv2);
    }
    __syncthreads();

    int buf = 0;
    for (int t = blockIdx.x; t < NT; t += GRID) {
        const int  nxt = t + GRID;
        const bool hn  = nxt < NT;
        const long t0n = (long)nxt * TM;

        if (wid < 4) {
            // -------- producers: rows 0..23 of tile t+GRID (items 0..767) --------
            if (hn) {
                float* An = &A[buf ^ 1][0][0];
                #pragma unroll
                for (int q = 0; q < 3; q++) {
                    const int i = tid + q * 256;          // tid in [0,128)
                    produce_pair(An, t0n, i, i + 128,
                                 src, src_neg, dst, dst_neg, inv2);
                }
            }
        } else {
            // -------- consumers: column-paired FFMA2 GEMM of tile t --------
            const int cw = wid - 4;
            const int r0 = cw << 3;
            const int c0 = lane << 2;
            const float* Ab = &A[buf][0][0];

            u64 acc[8][2];
            #pragma unroll
            for (int j = 0; j < 8; j++) { acc[j][0] = 0ull; acc[j][1] = 0ull; }

            #pragma unroll 4
            for (int k4 = 0; k4 < KDIM / 4; k4++) {
                float4 a[8];
                #pragma unroll
                for (int j = 0; j < 8; j++)
                    a[j] = ld4(Ab + (r0 + j) * A_STRIDE + (k4 << 2));  // broadcast LDS.128

                #pragma unroll
                for (int kk = 0; kk < 4; kk++) {
                    const float4 wv = ld4(w + (long)((k4 << 2) + kk) * OUTD + c0);
                    const u64 wp0 = reinterpret_cast<const u64*>(&wv)[0];
                    const u64 wp1 = reinterpret_cast<const u64*>(&wv)[1];
                    #pragma unroll
                    for (int j = 0; j < 8; j++) {
                        const u64 ap = bcast2((&a[j].x)[kk]);   // ALU-pipe pack
                        acc[j][0] = ffma2(ap, wp0, acc[j][0]);
                        acc[j][1] = ffma2(ap, wp1, acc[j][1]);
                    }
                }
            }

            const long row0 = (long)t * TM + r0;
            float* o = out + row0 * OUTD + c0;
            #pragma unroll
            for (int j = 0; j < 8; j++) {
                ulonglong2 r; r.x = acc[j][0]; r.y = acc[j][1];
                *reinterpret_cast<ulonglong2*>(o + (long)j * OUTD) = r;
            }

            // -------- slack window: rows 24..31 of tile t+GRID --------
            if (hn) {
                const int ctid = tid - 128;               // [0,128)
                produce_pair(&A[buf ^ 1][0][0], t0n, 768 + ctid, 768 + ctid + 128,
                             src, src_neg, dst, dst_neg, inv2);
            }
        }

        __syncthreads();
        buf ^= 1;
    }
}

extern "C" void kernel_launch(void* const* d_in, const int* in_sizes, int n_in,
                              void* d_out, int out_size)
{
    const float* src     = (const float*)d_in[0];
    const float* src_neg = (const float*)d_in[1];
    const float* dst     = (const float*)d_in[2];
    const float* dst_neg = (const float*)d_in[3];
    const float* w       = (const float*)d_in[4];
    float* out = (float*)d_out;

    magg_kernel<<<GRID, THREADS>>>(src, src_neg, dst, dst_neg, w, out);
}